// round 1
// baseline (speedup 1.0000x reference)
#include <cuda_runtime.h>
#include <math.h>

// Problem constants
// B=64, T=64, D=8, F=1024, H=1024, C=22, IN=4096, N=B*T=4096
#define NROWS 4096
#define FDIM  1024
#define HDIM  1024
#define INDIM 4096
#define DSTEPS 8
#define CDIM  22

// ---------------- scratch (device globals; no allocation allowed) -----------
__device__ float g_feats[NROWS * FDIM];       // 16 MB
__device__ float g_gates[NROWS * 4 * HDIM];   // 64 MB
__device__ float g_h[NROWS * HDIM];           // 16 MB
__device__ float g_c[NROWS * HDIM];           // 16 MB
__device__ float g_bsum_dec[4 * HDIM];
__device__ float g_bsum_enc[4 * FDIM];

// ---------------- generic GEMM: C[M,N] (+)= alpha * A[M,K] @ B[N,K]^T + bias -
// A row-major with lda, B row-major [N,K] with ldb, C row-major with ldc.
// M % 128 == 0 and K % 16 == 0 required (always true here); N guarded.
__global__ __launch_bounds__(256, 2)
void gemm_tn(const float* __restrict__ A, int lda,
             const float* __restrict__ B, int ldb,
             const float* __restrict__ bias,
             float* __restrict__ C, int ldc,
             int M, int N, int K,
             float alpha, int accumulate, int relu)
{
    __shared__ float As[16][132];
    __shared__ float Bs[16][132];

    const int tid = threadIdx.x;
    const int bm = blockIdx.y * 128;
    const int bn = blockIdx.x * 128;

    const int tm = (tid >> 4) << 3;   // 0..120 step 8
    const int tn = (tid & 15) << 3;   // 0..120 step 8

    const int lr = tid >> 2;          // 0..63
    const int lc = (tid & 3) << 2;    // 0,4,8,12

    float acc[8][8];
#pragma unroll
    for (int i = 0; i < 8; i++)
#pragma unroll
        for (int j = 0; j < 8; j++) acc[i][j] = 0.0f;

    for (int k0 = 0; k0 < K; k0 += 16) {
        // load A tile (128 x 16), transposed into As[k][m]
#pragma unroll
        for (int h = 0; h < 2; h++) {
            int r = lr + h * 64;
            const float4 v = *reinterpret_cast<const float4*>(
                &A[(size_t)(bm + r) * lda + k0 + lc]);
            As[lc + 0][r] = v.x; As[lc + 1][r] = v.y;
            As[lc + 2][r] = v.z; As[lc + 3][r] = v.w;
        }
        // load B tile (128 x 16), transposed into Bs[k][n], guard N
#pragma unroll
        for (int h = 0; h < 2; h++) {
            int r = lr + h * 64;
            float4 v = make_float4(0.f, 0.f, 0.f, 0.f);
            if (bn + r < N)
                v = *reinterpret_cast<const float4*>(
                    &B[(size_t)(bn + r) * ldb + k0 + lc]);
            Bs[lc + 0][r] = v.x; Bs[lc + 1][r] = v.y;
            Bs[lc + 2][r] = v.z; Bs[lc + 3][r] = v.w;
        }
        __syncthreads();

#pragma unroll
        for (int k = 0; k < 16; k++) {
            float a[8], b[8];
            *reinterpret_cast<float4*>(&a[0]) = *reinterpret_cast<const float4*>(&As[k][tm]);
            *reinterpret_cast<float4*>(&a[4]) = *reinterpret_cast<const float4*>(&As[k][tm + 4]);
            *reinterpret_cast<float4*>(&b[0]) = *reinterpret_cast<const float4*>(&Bs[k][tn]);
            *reinterpret_cast<float4*>(&b[4]) = *reinterpret_cast<const float4*>(&Bs[k][tn + 4]);
#pragma unroll
            for (int i = 0; i < 8; i++)
#pragma unroll
                for (int j = 0; j < 8; j++)
                    acc[i][j] += a[i] * b[j];
        }
        __syncthreads();
    }

    // epilogue
#pragma unroll
    for (int i = 0; i < 8; i++) {
        const int row = bm + tm + i;
        float* crow = C + (size_t)row * ldc;
#pragma unroll
        for (int j = 0; j < 8; j++) {
            const int col = bn + tn + j;
            if (col < N) {
                float v = acc[i][j] * alpha;
                if (bias) v += bias[col];
                if (accumulate) v += crow[col];
                if (relu) v = fmaxf(v, 0.0f);
                crow[col] = v;
            }
        }
    }
}

// ---------------- elementwise -----------------------------------------------
__global__ void add_bias2(const float* __restrict__ a, const float* __restrict__ b,
                          float* __restrict__ out, int n)
{
    int i = blockIdx.x * blockDim.x + threadIdx.x;
    if (i < n) out[i] = a[i] + b[i];
}

__device__ __forceinline__ float sigmoidf(float x) {
    return 1.0f / (1.0f + expf(-x));
}

// gates layout: [N, 4H] as (i, f, g, o) blocks of H.
__global__ void lstm_cell(const float* __restrict__ gates,
                          const float* __restrict__ c_in,
                          float* __restrict__ h_out,
                          float* __restrict__ c_out,
                          int N, int H, int czero)
{
    int idx = blockIdx.x * blockDim.x + threadIdx.x;
    if (idx >= N * H) return;
    int row = idx / H;
    int col = idx - row * H;
    const float* gr = gates + (size_t)row * 4 * H;
    float gi = sigmoidf(gr[col]);
    float gf = sigmoidf(gr[H + col]);
    float gg = tanhf(gr[2 * H + col]);
    float go = sigmoidf(gr[3 * H + col]);
    float cprev = czero ? 0.0f : c_in[idx];
    float cn = gf * cprev + gi * gg;
    c_out[idx] = cn;
    h_out[idx] = go * tanhf(cn);
}

// ---------------- launch ----------------------------------------------------
extern "C" void kernel_launch(void* const* d_in, const int* in_sizes, int n_in,
                              void* d_out, int out_size)
{
    const float* x    = (const float*)d_in[0];   // [N, 4096]
    const float* Wf   = (const float*)d_in[1];   // [1024, 4096]
    const float* bf   = (const float*)d_in[2];
    const float* dWih = (const float*)d_in[3];   // [4096, 1024]
    const float* dWhh = (const float*)d_in[4];   // [4096, 1024]
    const float* dbih = (const float*)d_in[5];
    const float* dbhh = (const float*)d_in[6];
    const float* Wdc  = (const float*)d_in[7];   // [1024, 1024]
    const float* bdc  = (const float*)d_in[8];
    const float* eWih = (const float*)d_in[9];   // [4096, 1024]
    const float* eWhh = (const float*)d_in[10];  // [4096, 1024]
    const float* ebih = (const float*)d_in[11];
    const float* ebhh = (const float*)d_in[12];
    const float* Wec  = (const float*)d_in[13];  // [22, 1024]
    const float* bec  = (const float*)d_in[14];

    float* out = (float*)d_out;
    float* dec = out + 64 * 64 * CDIM;   // dec_scores region: [N, D, F]

    float* feats = nullptr, *gates = nullptr, *h = nullptr, *c = nullptr;
    float* bsum_dec = nullptr, *bsum_enc = nullptr;
    cudaGetSymbolAddress((void**)&feats, g_feats);
    cudaGetSymbolAddress((void**)&gates, g_gates);
    cudaGetSymbolAddress((void**)&h, g_h);
    cudaGetSymbolAddress((void**)&c, g_c);
    cudaGetSymbolAddress((void**)&bsum_dec, g_bsum_dec);
    cudaGetSymbolAddress((void**)&bsum_enc, g_bsum_enc);

    const dim3 blk(256);

    // feats = relu(x @ Wf^T + bf)   M=4096 N=1024 K=4096
    {
        dim3 grid(FDIM / 128, NROWS / 128);
        gemm_tn<<<grid, blk>>>(x, INDIM, Wf, INDIM, bf, feats, FDIM,
                               NROWS, FDIM, INDIM, 1.0f, 0, 1);
    }
    add_bias2<<<(4 * HDIM + 255) / 256, blk>>>(dbih, dbhh, bsum_dec, 4 * HDIM);
    add_bias2<<<(4 * FDIM + 255) / 256, blk>>>(ebih, ebhh, bsum_enc, 4 * FDIM);

    // ---------------- decoder: 8 recurrent steps ----------------
    for (int d = 0; d < DSTEPS; d++) {
        const float* inp = (d == 0) ? feats : (dec + (size_t)(d - 1) * FDIM);
        const int lda = (d == 0) ? FDIM : (DSTEPS * FDIM);

        dim3 grid_g(4 * HDIM / 128, NROWS / 128);
        // gates = inp @ dWih^T + (bih+bhh)
        gemm_tn<<<grid_g, blk>>>(inp, lda, dWih, FDIM, bsum_dec, gates, 4 * HDIM,
                                 NROWS, 4 * HDIM, FDIM, 1.0f, 0, 0);
        if (d > 0) {
            // gates += h @ dWhh^T
            gemm_tn<<<grid_g, blk>>>(h, HDIM, dWhh, HDIM, nullptr, gates, 4 * HDIM,
                                     NROWS, 4 * HDIM, HDIM, 1.0f, 1, 0);
        }
        lstm_cell<<<(NROWS * HDIM + 255) / 256, blk>>>(gates, c, h, c,
                                                       NROWS, HDIM, d == 0 ? 1 : 0);
        // out_d = h @ Wdc^T + bdc  -> dec[:, d, :] (ldc = D*F)
        dim3 grid_o(FDIM / 128, NROWS / 128);
        gemm_tn<<<grid_o, blk>>>(h, HDIM, Wdc, HDIM, bdc,
                                 dec + (size_t)d * FDIM, DSTEPS * FDIM,
                                 NROWS, FDIM, HDIM, 1.0f, 0, 0);
    }

    // ---------------- encoder: one LSTM step ----------------
    {
        dim3 grid_g(4 * FDIM / 128, NROWS / 128);
        // gates = feats @ eWih^T + (ebih+ebhh)
        gemm_tn<<<grid_g, blk>>>(feats, FDIM, eWih, FDIM, bsum_enc, gates, 4 * FDIM,
                                 NROWS, 4 * FDIM, FDIM, 1.0f, 0, 0);
        // gates += (1/D) * last_out @ eWhh^T   (enc_h0 = last decoder out / D)
        gemm_tn<<<grid_g, blk>>>(dec + (size_t)(DSTEPS - 1) * FDIM, DSTEPS * FDIM,
                                 eWhh, FDIM, nullptr, gates, 4 * FDIM,
                                 NROWS, 4 * FDIM, FDIM, 1.0f / DSTEPS, 1, 0);
        // enc cell with c0 = 0
        lstm_cell<<<(NROWS * FDIM + 255) / 256, blk>>>(gates, nullptr, h, c,
                                                       NROWS, FDIM, 1);
        // enc_scores = h @ Wec^T + bec   M=4096 N=22 K=1024
        dim3 grid_s((CDIM + 127) / 128, NROWS / 128);
        gemm_tn<<<grid_s, blk>>>(h, FDIM, Wec, FDIM, bec, out, CDIM,
                                 NROWS, CDIM, FDIM, 1.0f, 0, 0);
    }
}

// round 3
// speedup vs baseline: 3.0867x; 3.0867x over previous
#include <cuda_runtime.h>
#include <cuda_bf16.h>
#include <stdint.h>
#include <math.h>

// B=64, T=64, D=8, F=1024, H=1024, C=22, IN=4096, N=B*T=4096
#define NROWS 4096
#define FDIM  1024
#define HDIM  1024
#define INDIM 4096
#define DSTEPS 8
#define CDIM  22

typedef __nv_bfloat16 bf16;

// ---------------- scratch (device globals) ----------------------------------
__device__ float g_gates[NROWS * 4 * FDIM];
__device__ float g_h[NROWS * HDIM];
__device__ float g_c[NROWS * HDIM];
__device__ float g_bsum_dec[4 * HDIM];
__device__ float g_bsum_enc[4 * FDIM];
__device__ float g_feats[NROWS * FDIM];

__device__ __align__(256) bf16 g_xh[NROWS * INDIM],  g_xl[NROWS * INDIM];
__device__ __align__(256) bf16 g_Wfh[FDIM * INDIM],  g_Wfl[FDIM * INDIM];
__device__ __align__(256) bf16 g_dWihh[4 * HDIM * FDIM], g_dWihl[4 * HDIM * FDIM];
__device__ __align__(256) bf16 g_dWhhh[4 * HDIM * HDIM], g_dWhhl[4 * HDIM * HDIM];
__device__ __align__(256) bf16 g_Wdch[FDIM * HDIM],  g_Wdcl[FDIM * HDIM];
__device__ __align__(256) bf16 g_eWihh[4 * FDIM * FDIM], g_eWihl[4 * FDIM * FDIM];
__device__ __align__(256) bf16 g_eWhhh[4 * FDIM * FDIM], g_eWhhl[4 * FDIM * FDIM];
__device__ __align__(256) bf16 g_fh[NROWS * FDIM],   g_fl[NROWS * FDIM];
__device__ __align__(256) bf16 g_hh[NROWS * HDIM],   g_hl[NROWS * HDIM];
__device__ __align__(256) bf16 g_dh[NROWS * FDIM],   g_dl[NROWS * FDIM];

// ---------------- PTX helpers ------------------------------------------------
__device__ __forceinline__ uint32_t smem_u32(const void* p) {
    uint32_t a;
    asm("{ .reg .u64 t; cvta.to.shared.u64 t, %1; cvt.u32.u64 %0, t; }" : "=r"(a) : "l"(p));
    return a;
}
__device__ __forceinline__ void cpa16(uint32_t sa, const void* g) {
    asm volatile("cp.async.cg.shared.global [%0], [%1], 16;" :: "r"(sa), "l"(g));
}
__device__ __forceinline__ void cp_commit() {
    asm volatile("cp.async.commit_group;" ::: "memory");
}
template<int N> __device__ __forceinline__ void cp_wait() {
    asm volatile("cp.async.wait_group %0;" :: "n"(N) : "memory");
}
__device__ __forceinline__ void ldmx4(uint32_t* r, uint32_t addr) {
    asm volatile("ldmatrix.sync.aligned.m8n8.x4.shared.b16 {%0,%1,%2,%3}, [%4];"
                 : "=r"(r[0]), "=r"(r[1]), "=r"(r[2]), "=r"(r[3]) : "r"(addr));
}
__device__ __forceinline__ void mma16816(float* c, const uint32_t* a, const uint32_t* b) {
    asm volatile("mma.sync.aligned.m16n8k16.row.col.f32.bf16.bf16.f32 "
                 "{%0,%1,%2,%3}, {%4,%5,%6,%7}, {%8,%9}, {%0,%1,%2,%3};"
                 : "+f"(c[0]), "+f"(c[1]), "+f"(c[2]), "+f"(c[3])
                 : "r"(a[0]), "r"(a[1]), "r"(a[2]), "r"(a[3]), "r"(b[0]), "r"(b[1]));
}

// SW128 swizzle over 128-byte rows: 8 groups of 16B, XOR with row&7.
__device__ __forceinline__ uint32_t swz(int row, int g) {
    return (uint32_t)(row * 128 + ((g ^ (row & 7)) << 4));
}

// ---------------- tensor GEMM ------------------------------------------------
// C[128,128] tile = sum over (Ahi+Alo)[128,K] @ (Bhi+Blo)[128,K]^T (lo*lo dropped)
// Two sequential K-sources (for gates = x@Wih^T + h@Whh^T). Bias/relu/bf16-pair
// emission fused into the epilogue.
#define T_AH 0
#define T_AL 16384
#define T_BH 32768
#define T_BL 49152
#define STAGE_SZ 65536
#define TG_SMEM (2 * STAGE_SZ)

__global__ __launch_bounds__(256, 1)
void tgemm(const bf16* __restrict__ A1h, const bf16* __restrict__ A1l, int lda1,
           const bf16* __restrict__ B1h, const bf16* __restrict__ B1l, int ldb1, int nk1,
           const bf16* __restrict__ A2h, const bf16* __restrict__ A2l, int lda2,
           const bf16* __restrict__ B2h, const bf16* __restrict__ B2l, int ldb2, int nk2,
           const float* __restrict__ bias, float* __restrict__ C, int ldc,
           bf16* __restrict__ Eh, bf16* __restrict__ El, int lde, float escale, int relu)
{
    extern __shared__ __align__(1024) char sm[];
    const int tid = threadIdx.x;
    const int wid = tid >> 5;
    const int lane = tid & 31;
    const int wm = wid >> 2;          // 0..1 : 64 rows each
    const int wn = wid & 3;           // 0..3 : 32 cols each
    const int bm = blockIdx.y * 128;
    const int bn = blockIdx.x * 128;
    const uint32_t smb = smem_u32(sm);
    const int total = nk1 + nk2;

    float acc[4][4][4];
#pragma unroll
    for (int i = 0; i < 4; i++)
#pragma unroll
        for (int j = 0; j < 4; j++)
#pragma unroll
            for (int k = 0; k < 4; k++) acc[i][j][k] = 0.0f;

    // ---- stage loader ----
    auto load_stage = [&](int q, int s) {
        const bf16 *ah, *al, *bh, *bl; int la, lb, k0;
        if (q < nk1) { ah = A1h; al = A1l; bh = B1h; bl = B1l; la = lda1; lb = ldb1; k0 = q * 64; }
        else         { ah = A2h; al = A2l; bh = B2h; bl = B2l; la = lda2; lb = ldb2; k0 = (q - nk1) * 64; }
        const uint32_t sb = smb + (uint32_t)s * STAGE_SZ;
#pragma unroll
        for (int i = 0; i < 4; i++) {
            int v = tid + i * 256;     // 0..1023
            int row = v >> 3, g = v & 7;
            uint32_t so = swz(row, g);
            cpa16(sb + T_AH + so, ah + (size_t)(bm + row) * la + k0 + g * 8);
            cpa16(sb + T_AL + so, al + (size_t)(bm + row) * la + k0 + g * 8);
            cpa16(sb + T_BH + so, bh + (size_t)(bn + row) * lb + k0 + g * 8);
            cpa16(sb + T_BL + so, bl + (size_t)(bn + row) * lb + k0 + g * 8);
        }
        cp_commit();
    };

    // ---- per-thread ldmatrix row/group bases ----
    const int r8 = lane & 7;
    const int arow0 = wm * 64 + r8 + 8 * ((lane >> 3) & 1);
    const int akq   = lane >> 4;                    // k-group select for A
    const int brow0 = wn * 32 + r8 + 8 * (lane >> 4);
    const int bkq   = (lane >> 3) & 1;              // k-group select for B

    load_stage(0, 0);

    for (int q = 0; q < total; q++) {
        const int s = q & 1;
        if (q + 1 < total) { load_stage(q + 1, s ^ 1); cp_wait<1>(); }
        else               { cp_wait<0>(); }
        __syncthreads();

        const uint32_t sb = smb + (uint32_t)s * STAGE_SZ;
#pragma unroll
        for (int ks = 0; ks < 4; ks++) {
            uint32_t a_h[4][4], a_l[4][4], b_h[4][2], b_l[4][2];
#pragma unroll
            for (int mt = 0; mt < 4; mt++) {
                uint32_t off = swz(arow0 + mt * 16, ks * 2 + akq);
                ldmx4(a_h[mt], sb + T_AH + off);
                ldmx4(a_l[mt], sb + T_AL + off);
            }
#pragma unroll
            for (int p = 0; p < 2; p++) {
                uint32_t off = swz(brow0 + p * 16, ks * 2 + bkq);
                uint32_t t[4];
                ldmx4(t, sb + T_BH + off);
                b_h[2 * p][0] = t[0]; b_h[2 * p][1] = t[1];
                b_h[2 * p + 1][0] = t[2]; b_h[2 * p + 1][1] = t[3];
                ldmx4(t, sb + T_BL + off);
                b_l[2 * p][0] = t[0]; b_l[2 * p][1] = t[1];
                b_l[2 * p + 1][0] = t[2]; b_l[2 * p + 1][1] = t[3];
            }
#pragma unroll
            for (int mt = 0; mt < 4; mt++)
#pragma unroll
                for (int nt = 0; nt < 4; nt++) {
                    mma16816(acc[mt][nt], a_h[mt], b_h[nt]);
                    mma16816(acc[mt][nt], a_h[mt], b_l[nt]);
                    mma16816(acc[mt][nt], a_l[mt], b_h[nt]);
                }
        }
        __syncthreads();
    }

    // ---- epilogue ----
#pragma unroll
    for (int mt = 0; mt < 4; mt++) {
#pragma unroll
        for (int nt = 0; nt < 4; nt++) {
            const int row = bm + wm * 64 + mt * 16 + (lane >> 2);
            const int col = bn + wn * 32 + nt * 8 + (lane & 3) * 2;
#pragma unroll
            for (int hh2 = 0; hh2 < 2; hh2++) {
                const int rr = row + hh2 * 8;
                float v0 = acc[mt][nt][2 * hh2];
                float v1 = acc[mt][nt][2 * hh2 + 1];
                if (bias) { v0 += bias[col]; v1 += bias[col + 1]; }
                if (relu) { v0 = fmaxf(v0, 0.0f); v1 = fmaxf(v1, 0.0f); }
                *reinterpret_cast<float2*>(C + (size_t)rr * ldc + col) = make_float2(v0, v1);
                if (Eh) {
                    float s0 = v0 * escale, s1 = v1 * escale;
                    bf16 h0 = __float2bfloat16(s0), h1 = __float2bfloat16(s1);
                    __nv_bfloat162 hp; hp.x = h0; hp.y = h1;
                    __nv_bfloat162 lp;
                    lp.x = __float2bfloat16(s0 - __bfloat162float(h0));
                    lp.y = __float2bfloat16(s1 - __bfloat162float(h1));
                    *reinterpret_cast<__nv_bfloat162*>(Eh + (size_t)rr * lde + col) = hp;
                    *reinterpret_cast<__nv_bfloat162*>(El + (size_t)rr * lde + col) = lp;
                }
            }
        }
    }
}

// ---------------- SIMT GEMM for tiny N=22 ------------------------------------
__global__ __launch_bounds__(256, 2)
void gemm_tn(const float* __restrict__ A, int lda,
             const float* __restrict__ B, int ldb,
             const float* __restrict__ bias,
             float* __restrict__ C, int ldc,
             int M, int N, int K)
{
    __shared__ float As[16][132];
    __shared__ float Bs[16][132];
    const int tid = threadIdx.x;
    const int bm = blockIdx.y * 128;
    const int bn = blockIdx.x * 128;
    const int tm = (tid >> 4) << 3;
    const int tn = (tid & 15) << 3;
    const int lr = tid >> 2;
    const int lc = (tid & 3) << 2;

    float acc[8][8];
#pragma unroll
    for (int i = 0; i < 8; i++)
#pragma unroll
        for (int j = 0; j < 8; j++) acc[i][j] = 0.0f;

    for (int k0 = 0; k0 < K; k0 += 16) {
#pragma unroll
        for (int h2 = 0; h2 < 2; h2++) {
            int r = lr + h2 * 64;
            const float4 v = *reinterpret_cast<const float4*>(&A[(size_t)(bm + r) * lda + k0 + lc]);
            As[lc + 0][r] = v.x; As[lc + 1][r] = v.y;
            As[lc + 2][r] = v.z; As[lc + 3][r] = v.w;
        }
#pragma unroll
        for (int h2 = 0; h2 < 2; h2++) {
            int r = lr + h2 * 64;
            float4 v = make_float4(0.f, 0.f, 0.f, 0.f);
            if (bn + r < N)
                v = *reinterpret_cast<const float4*>(&B[(size_t)(bn + r) * ldb + k0 + lc]);
            Bs[lc + 0][r] = v.x; Bs[lc + 1][r] = v.y;
            Bs[lc + 2][r] = v.z; Bs[lc + 3][r] = v.w;
        }
        __syncthreads();
#pragma unroll
        for (int k = 0; k < 16; k++) {
            float a[8], b[8];
            *reinterpret_cast<float4*>(&a[0]) = *reinterpret_cast<const float4*>(&As[k][tm]);
            *reinterpret_cast<float4*>(&a[4]) = *reinterpret_cast<const float4*>(&As[k][tm + 4]);
            *reinterpret_cast<float4*>(&b[0]) = *reinterpret_cast<const float4*>(&Bs[k][tn]);
            *reinterpret_cast<float4*>(&b[4]) = *reinterpret_cast<const float4*>(&Bs[k][tn + 4]);
#pragma unroll
            for (int i = 0; i < 8; i++)
#pragma unroll
                for (int j = 0; j < 8; j++)
                    acc[i][j] += a[i] * b[j];
        }
        __syncthreads();
    }
#pragma unroll
    for (int i = 0; i < 8; i++) {
        const int row = bm + tm + i;
        float* crow = C + (size_t)row * ldc;
#pragma unroll
        for (int j = 0; j < 8; j++) {
            const int col = bn + tn + j;
            if (col < N) {
                float v = acc[i][j];
                if (bias) v += bias[col];
                crow[col] = v;
            }
        }
    }
}

// ---------------- elementwise ------------------------------------------------
__global__ void add_bias2(const float* __restrict__ a, const float* __restrict__ b,
                          float* __restrict__ out, int n)
{
    int i = blockIdx.x * blockDim.x + threadIdx.x;
    if (i < n) out[i] = a[i] + b[i];
}

__global__ void cvt_pair(const float* __restrict__ src,
                         bf16* __restrict__ hi, bf16* __restrict__ lo, int n)
{
    int i = (blockIdx.x * blockDim.x + threadIdx.x) * 4;
    if (i >= n) return;
    float4 v = *reinterpret_cast<const float4*>(src + i);
    float f[4] = { v.x, v.y, v.z, v.w };
    __nv_bfloat162 h0, h1, l0, l1;
    bf16 a0 = __float2bfloat16(f[0]); bf16 a1 = __float2bfloat16(f[1]);
    bf16 a2 = __float2bfloat16(f[2]); bf16 a3 = __float2bfloat16(f[3]);
    h0.x = a0; h0.y = a1; h1.x = a2; h1.y = a3;
    l0.x = __float2bfloat16(f[0] - __bfloat162float(a0));
    l0.y = __float2bfloat16(f[1] - __bfloat162float(a1));
    l1.x = __float2bfloat16(f[2] - __bfloat162float(a2));
    l1.y = __float2bfloat16(f[3] - __bfloat162float(a3));
    *reinterpret_cast<__nv_bfloat162*>(hi + i) = h0;
    *reinterpret_cast<__nv_bfloat162*>(hi + i + 2) = h1;
    *reinterpret_cast<__nv_bfloat162*>(lo + i) = l0;
    *reinterpret_cast<__nv_bfloat162*>(lo + i + 2) = l1;
}

__device__ __forceinline__ float sigmoidf_(float x) { return 1.0f / (1.0f + expf(-x)); }

__global__ void lstm_cell(const float* __restrict__ gates,
                          const float* __restrict__ c_in,
                          float* __restrict__ h_out,
                          float* __restrict__ c_out,
                          bf16* __restrict__ hh, bf16* __restrict__ hl,
                          int N, int H, int czero)
{
    int idx = blockIdx.x * blockDim.x + threadIdx.x;
    if (idx >= N * H) return;
    int row = idx / H;
    int col = idx - row * H;
    const float* gr = gates + (size_t)row * 4 * H;
    float gi = sigmoidf_(gr[col]);
    float gf = sigmoidf_(gr[H + col]);
    float gg = tanhf(gr[2 * H + col]);
    float go = sigmoidf_(gr[3 * H + col]);
    float cprev = czero ? 0.0f : c_in[idx];
    float cn = gf * cprev + gi * gg;
    c_out[idx] = cn;
    float hn = go * tanhf(cn);
    h_out[idx] = hn;
    if (hh) {
        bf16 a = __float2bfloat16(hn);
        hh[idx] = a;
        hl[idx] = __float2bfloat16(hn - __bfloat162float(a));
    }
}

// ---------------- launch -----------------------------------------------------
extern "C" void kernel_launch(void* const* d_in, const int* in_sizes, int n_in,
                              void* d_out, int out_size)
{
    const float* x    = (const float*)d_in[0];
    const float* Wf   = (const float*)d_in[1];
    const float* bf_  = (const float*)d_in[2];
    const float* dWih = (const float*)d_in[3];
    const float* dWhh = (const float*)d_in[4];
    const float* dbih = (const float*)d_in[5];
    const float* dbhh = (const float*)d_in[6];
    const float* Wdc  = (const float*)d_in[7];
    const float* bdc  = (const float*)d_in[8];
    const float* eWih = (const float*)d_in[9];
    const float* eWhh = (const float*)d_in[10];
    const float* ebih = (const float*)d_in[11];
    const float* ebhh = (const float*)d_in[12];
    const float* Wec  = (const float*)d_in[13];
    const float* bec  = (const float*)d_in[14];

    float* out = (float*)d_out;
    float* dec = out + 64 * 64 * CDIM;

    float *gates, *h, *c, *bsd, *bse;
    bf16 *xh, *xl, *Wfh, *Wfl, *dWihh_, *dWihl_, *dWhhh_, *dWhhl_, *Wdch, *Wdcl;
    bf16 *eWihh_, *eWihl_, *eWhhh_, *eWhhl_, *fh, *fl, *hh, *hl, *dh, *dl;
    float* feats;
    cudaGetSymbolAddress((void**)&gates, g_gates);
    cudaGetSymbolAddress((void**)&h, g_h);
    cudaGetSymbolAddress((void**)&c, g_c);
    cudaGetSymbolAddress((void**)&bsd, g_bsum_dec);
    cudaGetSymbolAddress((void**)&bse, g_bsum_enc);
    cudaGetSymbolAddress((void**)&feats, g_feats);
    cudaGetSymbolAddress((void**)&xh, g_xh);   cudaGetSymbolAddress((void**)&xl, g_xl);
    cudaGetSymbolAddress((void**)&Wfh, g_Wfh); cudaGetSymbolAddress((void**)&Wfl, g_Wfl);
    cudaGetSymbolAddress((void**)&dWihh_, g_dWihh); cudaGetSymbolAddress((void**)&dWihl_, g_dWihl);
    cudaGetSymbolAddress((void**)&dWhhh_, g_dWhhh); cudaGetSymbolAddress((void**)&dWhhl_, g_dWhhl);
    cudaGetSymbolAddress((void**)&Wdch, g_Wdch); cudaGetSymbolAddress((void**)&Wdcl, g_Wdcl);
    cudaGetSymbolAddress((void**)&eWihh_, g_eWihh); cudaGetSymbolAddress((void**)&eWihl_, g_eWihl);
    cudaGetSymbolAddress((void**)&eWhhh_, g_eWhhh); cudaGetSymbolAddress((void**)&eWhhl_, g_eWhhl);
    cudaGetSymbolAddress((void**)&fh, g_fh);   cudaGetSymbolAddress((void**)&fl, g_fl);
    cudaGetSymbolAddress((void**)&hh, g_hh);   cudaGetSymbolAddress((void**)&hl, g_hl);
    cudaGetSymbolAddress((void**)&dh, g_dh);   cudaGetSymbolAddress((void**)&dl, g_dl);

    cudaFuncSetAttribute(tgemm, cudaFuncAttributeMaxDynamicSharedMemorySize, TG_SMEM);

    const dim3 blk(256);
    // conversions to bf16 hi/lo pairs
    cvt_pair<<<NROWS * INDIM / 4 / 256, blk>>>(x, xh, xl, NROWS * INDIM);
    cvt_pair<<<FDIM * INDIM / 4 / 256, blk>>>(Wf, Wfh, Wfl, FDIM * INDIM);
    cvt_pair<<<4 * HDIM * FDIM / 4 / 256, blk>>>(dWih, dWihh_, dWihl_, 4 * HDIM * FDIM);
    cvt_pair<<<4 * HDIM * HDIM / 4 / 256, blk>>>(dWhh, dWhhh_, dWhhl_, 4 * HDIM * HDIM);
    cvt_pair<<<FDIM * HDIM / 4 / 256, blk>>>(Wdc, Wdch, Wdcl, FDIM * HDIM);
    cvt_pair<<<4 * FDIM * FDIM / 4 / 256, blk>>>(eWih, eWihh_, eWihl_, 4 * FDIM * FDIM);
    cvt_pair<<<4 * FDIM * FDIM / 4 / 256, blk>>>(eWhh, eWhhh_, eWhhl_, 4 * FDIM * FDIM);
    add_bias2<<<(4 * HDIM + 255) / 256, blk>>>(dbih, dbhh, bsd, 4 * HDIM);
    add_bias2<<<(4 * FDIM + 255) / 256, blk>>>(ebih, ebhh, bse, 4 * FDIM);

    // feats = relu(x @ Wf^T + bf); emit bf16 pair
    tgemm<<<dim3(FDIM / 128, NROWS / 128), blk, TG_SMEM>>>(
        xh, xl, INDIM, Wfh, Wfl, INDIM, INDIM / 64,
        nullptr, nullptr, 0, nullptr, nullptr, 0, 0,
        bf_, feats, FDIM, fh, fl, FDIM, 1.0f, 1);

    // decoder: 8 recurrent steps
    for (int d = 0; d < DSTEPS; d++) {
        const bf16* ih = (d == 0) ? fh : dh;
        const bf16* il = (d == 0) ? fl : dl;
        tgemm<<<dim3(4 * HDIM / 128, NROWS / 128), blk, TG_SMEM>>>(
            ih, il, FDIM, dWihh_, dWihl_, FDIM, FDIM / 64,
            (d > 0) ? hh : nullptr, (d > 0) ? hl : nullptr, HDIM,
            dWhhh_, dWhhl_, HDIM, (d > 0) ? HDIM / 64 : 0,
            bsd, gates, 4 * HDIM, nullptr, nullptr, 0, 1.0f, 0);
        lstm_cell<<<NROWS * HDIM / 256, blk>>>(
            gates, c, h, c, hh, hl, NROWS, HDIM, d == 0 ? 1 : 0);
        tgemm<<<dim3(FDIM / 128, NROWS / 128), blk, TG_SMEM>>>(
            hh, hl, HDIM, Wdch, Wdcl, HDIM, HDIM / 64,
            nullptr, nullptr, 0, nullptr, nullptr, 0, 0,
            bdc, dec + (size_t)d * FDIM, DSTEPS * FDIM,
            dh, dl, FDIM, (d == DSTEPS - 1) ? (1.0f / DSTEPS) : 1.0f, 0);
    }

    // encoder
    tgemm<<<dim3(4 * FDIM / 128, NROWS / 128), blk, TG_SMEM>>>(
        fh, fl, FDIM, eWihh_, eWihl_, FDIM, FDIM / 64,
        dh, dl, FDIM, eWhhh_, eWhhl_, FDIM, FDIM / 64,
        bse, gates, 4 * FDIM, nullptr, nullptr, 0, 1.0f, 0);
    lstm_cell<<<NROWS * FDIM / 256, blk>>>(
        gates, nullptr, h, c, nullptr, nullptr, NROWS, FDIM, 1);
    gemm_tn<<<dim3((CDIM + 127) / 128, NROWS / 128), blk>>>(
        h, FDIM, Wec, FDIM, bec, out, CDIM, NROWS, CDIM, FDIM);
}

// round 4
// speedup vs baseline: 4.0613x; 1.3158x over previous
#include <cuda_runtime.h>
#include <cuda_fp16.h>
#include <stdint.h>
#include <math.h>

// B=64, T=64, D=8, F=1024, H=1024, C=22, IN=4096, N=B*T=4096
#define NROWS 4096
#define FDIM  1024
#define HDIM  1024
#define INDIM 4096
#define DSTEPS 8
#define CDIM  22

// ---------------- scratch (device globals) ----------------------------------
__device__ float g_gates[NROWS * 4 * FDIM];
__device__ float g_h[NROWS * HDIM];
__device__ float g_c[NROWS * HDIM];
__device__ float g_bsum_dec[4 * HDIM];
__device__ float g_bsum_enc[4 * FDIM];
__device__ float g_feats[NROWS * FDIM];

__device__ __align__(256) __half g_x16[NROWS * INDIM];
__device__ __align__(256) __half g_Wfh[FDIM * INDIM],  g_Wfl[FDIM * INDIM];
__device__ __align__(256) __half g_dWihh[4 * HDIM * FDIM], g_dWihl[4 * HDIM * FDIM];
__device__ __align__(256) __half g_dWhhh[4 * HDIM * HDIM], g_dWhhl[4 * HDIM * HDIM];
__device__ __align__(256) __half g_Wdch[FDIM * HDIM],  g_Wdcl[FDIM * HDIM];
__device__ __align__(256) __half g_eWihh[4 * FDIM * FDIM], g_eWihl[4 * FDIM * FDIM];
__device__ __align__(256) __half g_eWhhh[4 * FDIM * FDIM], g_eWhhl[4 * FDIM * FDIM];
__device__ __align__(256) __half g_f16[NROWS * FDIM];
__device__ __align__(256) __half g_h16[NROWS * HDIM];
__device__ __align__(256) __half g_d16[NROWS * FDIM];

// ---------------- PTX helpers ------------------------------------------------
__device__ __forceinline__ uint32_t smem_u32(const void* p) {
    uint32_t a;
    asm("{ .reg .u64 t; cvta.to.shared.u64 t, %1; cvt.u32.u64 %0, t; }" : "=r"(a) : "l"(p));
    return a;
}
__device__ __forceinline__ void cpa16(uint32_t sa, const void* g) {
    asm volatile("cp.async.cg.shared.global [%0], [%1], 16;" :: "r"(sa), "l"(g));
}
__device__ __forceinline__ void cp_commit() {
    asm volatile("cp.async.commit_group;" ::: "memory");
}
template<int N> __device__ __forceinline__ void cp_wait() {
    asm volatile("cp.async.wait_group %0;" :: "n"(N) : "memory");
}
__device__ __forceinline__ void ldmx4(uint32_t* r, uint32_t addr) {
    asm volatile("ldmatrix.sync.aligned.m8n8.x4.shared.b16 {%0,%1,%2,%3}, [%4];"
                 : "=r"(r[0]), "=r"(r[1]), "=r"(r[2]), "=r"(r[3]) : "r"(addr));
}
__device__ __forceinline__ void mma16816(float* c, const uint32_t* a, const uint32_t* b) {
    asm volatile("mma.sync.aligned.m16n8k16.row.col.f32.f16.f16.f32 "
                 "{%0,%1,%2,%3}, {%4,%5,%6,%7}, {%8,%9}, {%0,%1,%2,%3};"
                 : "+f"(c[0]), "+f"(c[1]), "+f"(c[2]), "+f"(c[3])
                 : "r"(a[0]), "r"(a[1]), "r"(a[2]), "r"(a[3]), "r"(b[0]), "r"(b[1]));
}
// SW128 swizzle over 128-byte rows: 8 groups of 16B, XOR with row&7.
__device__ __forceinline__ uint32_t swz(int row, int g) {
    return (uint32_t)(row * 128 + ((g ^ (row & 7)) << 4));
}

// ---------------- tensor GEMM ------------------------------------------------
// C[128,256] tile = A[128,K]fp16 @ (B_hi + B_lo)[256,K]^T
// Two sequential K-sources (gates = x@Wih^T + h@Whh^T). Bias/relu/fp16 emission fused.
#define T_A  0
#define T_BH 16384
#define T_BL 49152
#define STAGE_SZ 81920
#define TG_SMEM (2 * STAGE_SZ)

__global__ __launch_bounds__(256, 1)
void tgemm(const __half* __restrict__ A1, int lda1,
           const __half* __restrict__ B1h, const __half* __restrict__ B1l, int ldb1, int nk1,
           const __half* __restrict__ A2, int lda2,
           const __half* __restrict__ B2h, const __half* __restrict__ B2l, int ldb2, int nk2,
           const float* __restrict__ bias, float* __restrict__ C, int ldc,
           __half* __restrict__ E, int lde, float escale, int relu)
{
    extern __shared__ __align__(1024) char sm[];
    const int tid = threadIdx.x;
    const int wid = tid >> 5;
    const int lane = tid & 31;
    const int wm = wid >> 2;          // 0..1 : 64 rows each
    const int wn = wid & 3;           // 0..3 : 64 cols each
    const int bm = blockIdx.y * 128;
    const int bn = blockIdx.x * 256;
    const uint32_t smb = smem_u32(sm);
    const int total = nk1 + nk2;

    float acc[4][8][4];
#pragma unroll
    for (int i = 0; i < 4; i++)
#pragma unroll
        for (int j = 0; j < 8; j++)
#pragma unroll
            for (int k = 0; k < 4; k++) acc[i][j][k] = 0.0f;

    auto load_stage = [&](int q, int s) {
        const __half *a, *bh, *bl; int la, lb, k0;
        if (q < nk1) { a = A1; bh = B1h; bl = B1l; la = lda1; lb = ldb1; k0 = q * 64; }
        else         { a = A2; bh = B2h; bl = B2l; la = lda2; lb = ldb2; k0 = (q - nk1) * 64; }
        const uint32_t sb = smb + (uint32_t)s * STAGE_SZ;
#pragma unroll
        for (int i = 0; i < 4; i++) {
            int v = tid + i * 256;     // 0..1023 : A 128 rows x 8 groups
            int row = v >> 3, g = v & 7;
            cpa16(sb + T_A + swz(row, g), a + (size_t)(bm + row) * la + k0 + g * 8);
        }
#pragma unroll
        for (int i = 0; i < 8; i++) {
            int v = tid + i * 256;     // 0..2047 : B 256 rows x 8 groups
            int row = v >> 3, g = v & 7;
            uint32_t so = swz(row, g);
            cpa16(sb + T_BH + so, bh + (size_t)(bn + row) * lb + k0 + g * 8);
            cpa16(sb + T_BL + so, bl + (size_t)(bn + row) * lb + k0 + g * 8);
        }
        cp_commit();
    };

    const int r8 = lane & 7;
    const int arow0 = wm * 64 + r8 + 8 * ((lane >> 3) & 1);
    const int akq   = lane >> 4;
    const int brow0 = wn * 64 + r8 + 8 * (lane >> 4);
    const int bkq   = (lane >> 3) & 1;

    load_stage(0, 0);

    for (int q = 0; q < total; q++) {
        const int s = q & 1;
        if (q + 1 < total) { load_stage(q + 1, s ^ 1); cp_wait<1>(); }
        else               { cp_wait<0>(); }
        __syncthreads();

        const uint32_t sb = smb + (uint32_t)s * STAGE_SZ;
#pragma unroll
        for (int ks = 0; ks < 4; ks++) {
            uint32_t a[4][4];
#pragma unroll
            for (int mt = 0; mt < 4; mt++)
                ldmx4(a[mt], sb + T_A + swz(arow0 + mt * 16, ks * 2 + akq));
            {
                uint32_t b[8][2];
#pragma unroll
                for (int p = 0; p < 4; p++) {
                    uint32_t t[4];
                    ldmx4(t, sb + T_BH + swz(brow0 + p * 16, ks * 2 + bkq));
                    b[2 * p][0] = t[0]; b[2 * p][1] = t[1];
                    b[2 * p + 1][0] = t[2]; b[2 * p + 1][1] = t[3];
                }
#pragma unroll
                for (int mt = 0; mt < 4; mt++)
#pragma unroll
                    for (int nt = 0; nt < 8; nt++)
                        mma16816(acc[mt][nt], a[mt], b[nt]);
            }
            {
                uint32_t b[8][2];
#pragma unroll
                for (int p = 0; p < 4; p++) {
                    uint32_t t[4];
                    ldmx4(t, sb + T_BL + swz(brow0 + p * 16, ks * 2 + bkq));
                    b[2 * p][0] = t[0]; b[2 * p][1] = t[1];
                    b[2 * p + 1][0] = t[2]; b[2 * p + 1][1] = t[3];
                }
#pragma unroll
                for (int mt = 0; mt < 4; mt++)
#pragma unroll
                    for (int nt = 0; nt < 8; nt++)
                        mma16816(acc[mt][nt], a[mt], b[nt]);
            }
        }
        __syncthreads();
    }

    // ---- epilogue ----
#pragma unroll
    for (int mt = 0; mt < 4; mt++) {
#pragma unroll
        for (int nt = 0; nt < 8; nt++) {
            const int row = bm + wm * 64 + mt * 16 + (lane >> 2);
            const int col = bn + wn * 64 + nt * 8 + (lane & 3) * 2;
#pragma unroll
            for (int hh2 = 0; hh2 < 2; hh2++) {
                const int rr = row + hh2 * 8;
                float v0 = acc[mt][nt][2 * hh2];
                float v1 = acc[mt][nt][2 * hh2 + 1];
                if (bias) { v0 += bias[col]; v1 += bias[col + 1]; }
                if (relu) { v0 = fmaxf(v0, 0.0f); v1 = fmaxf(v1, 0.0f); }
                *reinterpret_cast<float2*>(C + (size_t)rr * ldc + col) = make_float2(v0, v1);
                if (E) {
                    __half2 hp;
                    hp.x = __float2half_rn(v0 * escale);
                    hp.y = __float2half_rn(v1 * escale);
                    *reinterpret_cast<__half2*>(E + (size_t)rr * lde + col) = hp;
                }
            }
        }
    }
}

// ---------------- SIMT GEMM for tiny N=22 ------------------------------------
__global__ __launch_bounds__(256, 2)
void gemm_tn(const float* __restrict__ A, int lda,
             const float* __restrict__ B, int ldb,
             const float* __restrict__ bias,
             float* __restrict__ C, int ldc,
             int M, int N, int K)
{
    __shared__ float As[16][132];
    __shared__ float Bs[16][132];
    const int tid = threadIdx.x;
    const int bm = blockIdx.y * 128;
    const int bn = blockIdx.x * 128;
    const int tm = (tid >> 4) << 3;
    const int tn = (tid & 15) << 3;
    const int lr = tid >> 2;
    const int lc = (tid & 3) << 2;

    float acc[8][8];
#pragma unroll
    for (int i = 0; i < 8; i++)
#pragma unroll
        for (int j = 0; j < 8; j++) acc[i][j] = 0.0f;

    for (int k0 = 0; k0 < K; k0 += 16) {
#pragma unroll
        for (int h2 = 0; h2 < 2; h2++) {
            int r = lr + h2 * 64;
            const float4 v = *reinterpret_cast<const float4*>(&A[(size_t)(bm + r) * lda + k0 + lc]);
            As[lc + 0][r] = v.x; As[lc + 1][r] = v.y;
            As[lc + 2][r] = v.z; As[lc + 3][r] = v.w;
        }
#pragma unroll
        for (int h2 = 0; h2 < 2; h2++) {
            int r = lr + h2 * 64;
            float4 v = make_float4(0.f, 0.f, 0.f, 0.f);
            if (bn + r < N)
                v = *reinterpret_cast<const float4*>(&B[(size_t)(bn + r) * ldb + k0 + lc]);
            Bs[lc + 0][r] = v.x; Bs[lc + 1][r] = v.y;
            Bs[lc + 2][r] = v.z; Bs[lc + 3][r] = v.w;
        }
        __syncthreads();
#pragma unroll
        for (int k = 0; k < 16; k++) {
            float a[8], b[8];
            *reinterpret_cast<float4*>(&a[0]) = *reinterpret_cast<const float4*>(&As[k][tm]);
            *reinterpret_cast<float4*>(&a[4]) = *reinterpret_cast<const float4*>(&As[k][tm + 4]);
            *reinterpret_cast<float4*>(&b[0]) = *reinterpret_cast<const float4*>(&Bs[k][tn]);
            *reinterpret_cast<float4*>(&b[4]) = *reinterpret_cast<const float4*>(&Bs[k][tn + 4]);
#pragma unroll
            for (int i = 0; i < 8; i++)
#pragma unroll
                for (int j = 0; j < 8; j++)
                    acc[i][j] += a[i] * b[j];
        }
        __syncthreads();
    }
#pragma unroll
    for (int i = 0; i < 8; i++) {
        const int row = bm + tm + i;
        float* crow = C + (size_t)row * ldc;
#pragma unroll
        for (int j = 0; j < 8; j++) {
            const int col = bn + tn + j;
            if (col < N) {
                float v = acc[i][j];
                if (bias) v += bias[col];
                crow[col] = v;
            }
        }
    }
}

// ---------------- elementwise ------------------------------------------------
__global__ void add_bias2(const float* __restrict__ a, const float* __restrict__ b,
                          float* __restrict__ out, int n)
{
    int i = blockIdx.x * blockDim.x + threadIdx.x;
    if (i < n) out[i] = a[i] + b[i];
}

// weights: fp32 -> fp16 hi + fp16 lo
__global__ void cvt_wpair(const float* __restrict__ src,
                          __half* __restrict__ hi, __half* __restrict__ lo, int n)
{
    int i = (blockIdx.x * blockDim.x + threadIdx.x) * 4;
    if (i >= n) return;
    float4 v = *reinterpret_cast<const float4*>(src + i);
    float f[4] = { v.x, v.y, v.z, v.w };
    __half h[4], l[4];
#pragma unroll
    for (int k = 0; k < 4; k++) {
        h[k] = __float2half_rn(f[k]);
        l[k] = __float2half_rn(f[k] - __half2float(h[k]));
    }
    __half2 hp0; hp0.x = h[0]; hp0.y = h[1];
    __half2 hp1; hp1.x = h[2]; hp1.y = h[3];
    __half2 lp0; lp0.x = l[0]; lp0.y = l[1];
    __half2 lp1; lp1.x = l[2]; lp1.y = l[3];
    *reinterpret_cast<__half2*>(hi + i) = hp0;
    *reinterpret_cast<__half2*>(hi + i + 2) = hp1;
    *reinterpret_cast<__half2*>(lo + i) = lp0;
    *reinterpret_cast<__half2*>(lo + i + 2) = lp1;
}

// activations: fp32 -> fp16
__global__ void cvt_h(const float* __restrict__ src, __half* __restrict__ dst, int n)
{
    int i = (blockIdx.x * blockDim.x + threadIdx.x) * 4;
    if (i >= n) return;
    float4 v = *reinterpret_cast<const float4*>(src + i);
    __half2 p0; p0.x = __float2half_rn(v.x); p0.y = __float2half_rn(v.y);
    __half2 p1; p1.x = __float2half_rn(v.z); p1.y = __float2half_rn(v.w);
    *reinterpret_cast<__half2*>(dst + i) = p0;
    *reinterpret_cast<__half2*>(dst + i + 2) = p1;
}

__device__ __forceinline__ float sigmoidf_(float x) { return 1.0f / (1.0f + expf(-x)); }

__global__ void lstm_cell(const float* __restrict__ gates,
                          const float* __restrict__ c_in,
                          float* __restrict__ h_out,
                          float* __restrict__ c_out,
                          __half* __restrict__ h16,
                          int N, int H, int czero)
{
    int idx = blockIdx.x * blockDim.x + threadIdx.x;
    if (idx >= N * H) return;
    int row = idx / H;
    int col = idx - row * H;
    const float* gr = gates + (size_t)row * 4 * H;
    float gi = sigmoidf_(gr[col]);
    float gf = sigmoidf_(gr[H + col]);
    float gg = tanhf(gr[2 * H + col]);
    float go = sigmoidf_(gr[3 * H + col]);
    float cprev = czero ? 0.0f : c_in[idx];
    float cn = gf * cprev + gi * gg;
    c_out[idx] = cn;
    float hn = go * tanhf(cn);
    h_out[idx] = hn;
    if (h16) h16[idx] = __float2half_rn(hn);
}

// ---------------- launch -----------------------------------------------------
extern "C" void kernel_launch(void* const* d_in, const int* in_sizes, int n_in,
                              void* d_out, int out_size)
{
    const float* x    = (const float*)d_in[0];
    const float* Wf   = (const float*)d_in[1];
    const float* bf_  = (const float*)d_in[2];
    const float* dWih = (const float*)d_in[3];
    const float* dWhh = (const float*)d_in[4];
    const float* dbih = (const float*)d_in[5];
    const float* dbhh = (const float*)d_in[6];
    const float* Wdc  = (const float*)d_in[7];
    const float* bdc  = (const float*)d_in[8];
    const float* eWih = (const float*)d_in[9];
    const float* eWhh = (const float*)d_in[10];
    const float* ebih = (const float*)d_in[11];
    const float* ebhh = (const float*)d_in[12];
    const float* Wec  = (const float*)d_in[13];
    const float* bec  = (const float*)d_in[14];

    float* out = (float*)d_out;
    float* dec = out + 64 * 64 * CDIM;

    float *gates, *h, *c, *bsd, *bse, *feats;
    __half *x16, *Wfh, *Wfl, *dWihh_, *dWihl_, *dWhhh_, *dWhhl_, *Wdch, *Wdcl;
    __half *eWihh_, *eWihl_, *eWhhh_, *eWhhl_, *f16, *h16, *d16;
    cudaGetSymbolAddress((void**)&gates, g_gates);
    cudaGetSymbolAddress((void**)&h, g_h);
    cudaGetSymbolAddress((void**)&c, g_c);
    cudaGetSymbolAddress((void**)&bsd, g_bsum_dec);
    cudaGetSymbolAddress((void**)&bse, g_bsum_enc);
    cudaGetSymbolAddress((void**)&feats, g_feats);
    cudaGetSymbolAddress((void**)&x16, g_x16);
    cudaGetSymbolAddress((void**)&Wfh, g_Wfh); cudaGetSymbolAddress((void**)&Wfl, g_Wfl);
    cudaGetSymbolAddress((void**)&dWihh_, g_dWihh); cudaGetSymbolAddress((void**)&dWihl_, g_dWihl);
    cudaGetSymbolAddress((void**)&dWhhh_, g_dWhhh); cudaGetSymbolAddress((void**)&dWhhl_, g_dWhhl);
    cudaGetSymbolAddress((void**)&Wdch, g_Wdch); cudaGetSymbolAddress((void**)&Wdcl, g_Wdcl);
    cudaGetSymbolAddress((void**)&eWihh_, g_eWihh); cudaGetSymbolAddress((void**)&eWihl_, g_eWihl);
    cudaGetSymbolAddress((void**)&eWhhh_, g_eWhhh); cudaGetSymbolAddress((void**)&eWhhl_, g_eWhhl);
    cudaGetSymbolAddress((void**)&f16, g_f16);
    cudaGetSymbolAddress((void**)&h16, g_h16);
    cudaGetSymbolAddress((void**)&d16, g_d16);

    cudaFuncSetAttribute(tgemm, cudaFuncAttributeMaxDynamicSharedMemorySize, TG_SMEM);

    const dim3 blk(256);
    cvt_h<<<NROWS * INDIM / 4 / 256, blk>>>(x, x16, NROWS * INDIM);
    cvt_wpair<<<FDIM * INDIM / 4 / 256, blk>>>(Wf, Wfh, Wfl, FDIM * INDIM);
    cvt_wpair<<<4 * HDIM * FDIM / 4 / 256, blk>>>(dWih, dWihh_, dWihl_, 4 * HDIM * FDIM);
    cvt_wpair<<<4 * HDIM * HDIM / 4 / 256, blk>>>(dWhh, dWhhh_, dWhhl_, 4 * HDIM * HDIM);
    cvt_wpair<<<FDIM * HDIM / 4 / 256, blk>>>(Wdc, Wdch, Wdcl, FDIM * HDIM);
    cvt_wpair<<<4 * FDIM * FDIM / 4 / 256, blk>>>(eWih, eWihh_, eWihl_, 4 * FDIM * FDIM);
    cvt_wpair<<<4 * FDIM * FDIM / 4 / 256, blk>>>(eWhh, eWhhh_, eWhhl_, 4 * FDIM * FDIM);
    add_bias2<<<(4 * HDIM + 255) / 256, blk>>>(dbih, dbhh, bsd, 4 * HDIM);
    add_bias2<<<(4 * FDIM + 255) / 256, blk>>>(ebih, ebhh, bse, 4 * FDIM);

    // feats = relu(x @ Wf^T + bf); emit fp16
    tgemm<<<dim3(FDIM / 256, NROWS / 128), blk, TG_SMEM>>>(
        x16, INDIM, Wfh, Wfl, INDIM, INDIM / 64,
        nullptr, 0, nullptr, nullptr, 0, 0,
        bf_, feats, FDIM, f16, FDIM, 1.0f, 1);

    // decoder: 8 recurrent steps
    for (int d = 0; d < DSTEPS; d++) {
        const __half* inp = (d == 0) ? f16 : d16;
        tgemm<<<dim3(4 * HDIM / 256, NROWS / 128), blk, TG_SMEM>>>(
            inp, FDIM, dWihh_, dWihl_, FDIM, FDIM / 64,
            (d > 0) ? h16 : nullptr, HDIM,
            dWhhh_, dWhhl_, HDIM, (d > 0) ? HDIM / 64 : 0,
            bsd, gates, 4 * HDIM, nullptr, 0, 1.0f, 0);
        lstm_cell<<<NROWS * HDIM / 256, blk>>>(
            gates, c, h, c, h16, NROWS, HDIM, d == 0 ? 1 : 0);
        tgemm<<<dim3(FDIM / 256, NROWS / 128), blk, TG_SMEM>>>(
            h16, HDIM, Wdch, Wdcl, HDIM, HDIM / 64,
            nullptr, 0, nullptr, nullptr, 0, 0,
            bdc, dec + (size_t)d * FDIM, DSTEPS * FDIM,
            d16, FDIM, (d == DSTEPS - 1) ? (1.0f / DSTEPS) : 1.0f, 0);
    }

    // encoder
    tgemm<<<dim3(4 * FDIM / 256, NROWS / 128), blk, TG_SMEM>>>(
        f16, FDIM, eWihh_, eWihl_, FDIM, FDIM / 64,
        d16, FDIM, eWhhh_, eWhhl_, FDIM, FDIM / 64,
        bse, gates, 4 * FDIM, nullptr, 0, 1.0f, 0);
    lstm_cell<<<NROWS * FDIM / 256, blk>>>(
        gates, nullptr, h, c, nullptr, NROWS, FDIM, 1);
    gemm_tn<<<dim3((CDIM + 127) / 128, NROWS / 128), blk>>>(
        h, FDIM, Wec, FDIM, bec, out, CDIM, NROWS, CDIM, FDIM);
}